// round 2
// baseline (speedup 1.0000x reference)
#include <cuda_runtime.h>
#include <cuda_bf16.h>

#define STATE_DIM 512
#define AFEAT 64
#define HID 256
#define HID2 128
#define BATCH 256
#define KACT 1000
#define NROWS (BATCH * KACT)   // 256000

// h_state (+b1 folded) scratch: 256 x 256 fp32
__device__ float g_hstate[BATCH * HID];

// ---------------------------------------------------------------------------
// Kernel 1: h_state[b][j] = sum_k state[b][k] * W1[k][j] + b1[j]
// ---------------------------------------------------------------------------
__global__ __launch_bounds__(256) void hstate_kernel(
    const float* __restrict__ state,
    const float* __restrict__ W1,
    const float* __restrict__ b1)
{
    __shared__ float s[STATE_DIM];
    int b = blockIdx.x;
    int j = threadIdx.x;
    for (int k = threadIdx.x; k < STATE_DIM; k += 256)
        s[k] = state[b * STATE_DIM + k];
    __syncthreads();

    float acc = b1[j];
#pragma unroll 8
    for (int k = 0; k < STATE_DIM; k++)
        acc = fmaf(s[k], W1[k * HID + j], acc);
    g_hstate[b * HID + j] = acc;
}

// ---------------------------------------------------------------------------
// Kernel 2: fused 3-layer MLP over all 256000 rows.
// Block: 256 threads (8 warps). All weights resident in SMEM.
// Each warp processes 4 rows at a time, 8 iterations -> 256 rows/block.
// Grid: 1000 blocks.
//
// SMEM (floats):
//   sW1a : [256 cols][16 f4-chunks] float4, XOR-swizzled   -> 16384 floats
//   sW2  : [128 cols][64 g4-chunks] float4, XOR-swizzled   -> 32768 floats
//   sW3  : 128
//   sB2  : 128
//   wbuf : 8 warps * 1024 (union of a-stage 4x64 and h1 4x256)
// total = 57600 floats = 230400 B (opt-in dynamic smem)
// ---------------------------------------------------------------------------
#define SMEM_FLOATS 57600
#define SMEM_BYTES  (SMEM_FLOATS * 4)

#define OFF_W1A 0
#define OFF_W2  16384
#define OFF_W3  49152
#define OFF_B2  49280
#define OFF_WB  49408

__global__ __launch_bounds__(256, 1) void actor_main_kernel(
    const float* __restrict__ af,     // [256000][64]
    const float* __restrict__ W1,     // [576][256] (rows 512..575 = W1a)
    const float* __restrict__ W2,     // [256][128]
    const float* __restrict__ b2,     // [128]
    const float* __restrict__ W3,     // [128]
    const float* __restrict__ b3,     // [1]
    float* __restrict__ out)          // [256000]
{
    extern __shared__ float smem[];
    float* sW1a = smem + OFF_W1A;
    float* sW2  = smem + OFF_W2;
    float* sW3  = smem + OFF_W3;
    float* sB2  = smem + OFF_B2;

    const int t = threadIdx.x;

    // ---- Fill W1a: logical W1a[f][col] -> sW1a[col][f] (f4 XOR-swizzled) ----
    {
        int col = t;  // 0..255
#pragma unroll 4
        for (int f = 0; f < AFEAT; f++) {
            float v = W1[(STATE_DIM + f) * HID + col];   // coalesced over col
            int f4 = f >> 2, fl = f & 3;
            int f4s = f4 ^ (col & 15);
            sW1a[col * 64 + f4s * 4 + fl] = v;
        }
    }
    // ---- Fill W2: logical W2[g][col] -> sW2[col][g] (g4 low-bits swizzled) --
    {
        int col = t & 127;
        int gbase = (t >> 7) * 128;
#pragma unroll 4
        for (int gg = 0; gg < 128; gg++) {
            int g = gbase + gg;
            float v = W2[g * HID2 + col];                // coalesced over col
            int g4 = g >> 2, gl = g & 3;
            int g4s = (g4 & ~15) | ((g4 & 15) ^ (col & 15));
            sW2[col * 256 + g4s * 4 + gl] = v;
        }
    }
    if (t < 128) {
        sW3[t] = W3[t];
        sB2[t] = b2[t];
    }
    __syncthreads();

    const int warp = t >> 5;
    const int lane = t & 31;
    float* wbuf = smem + OFF_WB + warp * 1024;     // per-warp private
    const float  bias3 = __ldg(b3);
    const int block_base = blockIdx.x * 256;

    const float4* w1v = (const float4*)sW1a;       // [col][16]
    const float4* w2v = (const float4*)sW2;        // [col][64]

    for (int it = 0; it < 8; it++) {
        const int row0 = block_base + it * 32 + warp * 4;   // rows row0..row0+3

        // ---- stage 4 rows x 64 feats into wbuf (as 64 float4) ----
        {
            float4* av = (float4*)wbuf;
            int idx = lane;
            av[idx] = ((const float4*)af)[(long)(row0 + (idx >> 4)) * 16 + (idx & 15)];
            idx = lane + 32;
            av[idx] = ((const float4*)af)[(long)(row0 + (idx >> 4)) * 16 + (idx & 15)];
        }
        __syncwarp();

        // ---- Layer 1: h1[col] = relu( a . W1a[:,col] + hstate[b][col] ) ----
        float acc[8][4];
#pragma unroll
        for (int r = 0; r < 4; r++) {
            int b = (row0 + r) / KACT;
            const float* hsrow = g_hstate + b * HID;
#pragma unroll
            for (int jj = 0; jj < 8; jj++)
                acc[jj][r] = __ldg(hsrow + jj * 32 + lane);
        }
        const float4* a4v = (const float4*)wbuf;
#pragma unroll 4
        for (int f4 = 0; f4 < 16; f4++) {
            float4 a0 = a4v[0 * 16 + f4];
            float4 a1 = a4v[1 * 16 + f4];
            float4 a2 = a4v[2 * 16 + f4];
            float4 a3 = a4v[3 * 16 + f4];
            int f4s = f4 ^ (lane & 15);
#pragma unroll
            for (int jj = 0; jj < 8; jj++) {
                int col = jj * 32 + lane;
                float4 w = w1v[col * 16 + f4s];
                acc[jj][0] += w.x*a0.x + w.y*a0.y + w.z*a0.z + w.w*a0.w;
                acc[jj][1] += w.x*a1.x + w.y*a1.y + w.z*a1.z + w.w*a1.w;
                acc[jj][2] += w.x*a2.x + w.y*a2.y + w.z*a2.z + w.w*a2.w;
                acc[jj][3] += w.x*a3.x + w.y*a3.y + w.z*a3.z + w.w*a3.w;
            }
        }

        // ---- store relu(h1) into wbuf: [r][256] ----
        __syncwarp();
#pragma unroll
        for (int jj = 0; jj < 8; jj++)
#pragma unroll
            for (int r = 0; r < 4; r++)
                wbuf[r * 256 + jj * 32 + lane] = fmaxf(acc[jj][r], 0.0f);
        __syncwarp();

        // ---- Layer 2: h2[col] = relu( h1 . W2[:,col] + b2[col] ) ----
        float acc2[4][4];
#pragma unroll
        for (int jj2 = 0; jj2 < 4; jj2++) {
            float bb = sB2[jj2 * 32 + lane];
#pragma unroll
            for (int r = 0; r < 4; r++) acc2[jj2][r] = bb;
        }
        const float4* h1v = (const float4*)wbuf;   // [r][64]
#pragma unroll 4
        for (int g4 = 0; g4 < 64; g4++) {
            float4 h0 = h1v[0 * 64 + g4];
            float4 h1 = h1v[1 * 64 + g4];
            float4 h2 = h1v[2 * 64 + g4];
            float4 h3 = h1v[3 * 64 + g4];
            int g4s = (g4 & ~15) | ((g4 & 15) ^ (lane & 15));
#pragma unroll
            for (int jj2 = 0; jj2 < 4; jj2++) {
                int col = jj2 * 32 + lane;
                float4 w = w2v[col * 64 + g4s];
                acc2[jj2][0] += w.x*h0.x + w.y*h0.y + w.z*h0.z + w.w*h0.w;
                acc2[jj2][1] += w.x*h1.x + w.y*h1.y + w.z*h1.z + w.w*h1.w;
                acc2[jj2][2] += w.x*h2.x + w.y*h2.y + w.z*h2.z + w.w*h2.w;
                acc2[jj2][3] += w.x*h3.x + w.y*h3.y + w.z*h3.z + w.w*h3.w;
            }
        }

        // ---- Layer 3: logit = relu(h2) . W3 + b3, warp-reduce ----
        float part0 = 0.f, part1 = 0.f, part2 = 0.f, part3 = 0.f;
#pragma unroll
        for (int jj2 = 0; jj2 < 4; jj2++) {
            float w3 = sW3[jj2 * 32 + lane];
            part0 += fmaxf(acc2[jj2][0], 0.f) * w3;
            part1 += fmaxf(acc2[jj2][1], 0.f) * w3;
            part2 += fmaxf(acc2[jj2][2], 0.f) * w3;
            part3 += fmaxf(acc2[jj2][3], 0.f) * w3;
        }
#pragma unroll
        for (int off = 16; off > 0; off >>= 1) {
            part0 += __shfl_xor_sync(0xffffffffu, part0, off);
            part1 += __shfl_xor_sync(0xffffffffu, part1, off);
            part2 += __shfl_xor_sync(0xffffffffu, part2, off);
            part3 += __shfl_xor_sync(0xffffffffu, part3, off);
        }
        if (lane == 0) {
            out[row0 + 0] = part0 + bias3;
            out[row0 + 1] = part1 + bias3;
            out[row0 + 2] = part2 + bias3;
            out[row0 + 3] = part3 + bias3;
        }
        __syncwarp();   // protect wbuf reuse next iteration
    }
}

// ---------------------------------------------------------------------------
extern "C" void kernel_launch(void* const* d_in, const int* in_sizes, int n_in,
                              void* d_out, int out_size)
{
    const float* state = (const float*)d_in[0];
    const float* af    = (const float*)d_in[1];
    const float* W1    = (const float*)d_in[2];
    const float* b1    = (const float*)d_in[3];
    const float* W2    = (const float*)d_in[4];
    const float* b2    = (const float*)d_in[5];
    const float* W3    = (const float*)d_in[6];
    const float* b3    = (const float*)d_in[7];
    float* out = (float*)d_out;

    cudaFuncSetAttribute(actor_main_kernel,
                         cudaFuncAttributeMaxDynamicSharedMemorySize, SMEM_BYTES);

    hstate_kernel<<<BATCH, 256>>>(state, W1, b1);
    actor_main_kernel<<<NROWS / 256, 256, SMEM_BYTES>>>(af, W1, W2, b2, W3, b3, out);
}

// round 5
// speedup vs baseline: 3.5154x; 3.5154x over previous
#include <cuda_runtime.h>
#include <cstdint>

#define STATE_DIM 512
#define AFEAT 64
#define HID 256
#define HID2 128
#define KACT 1000
#define NROWS 256000
#define TILE_M 64
#define NTILES 4000            // 256000 / 64

__device__ float g_hstate[256 * HID];
__device__ __align__(16) float g_w1af[16384];   // W1a frag-ordered, 64 KB

__device__ __forceinline__ uint32_t f2tf(float f) {
    uint32_t r;
    asm("cvt.rna.tf32.f32 %0, %1;" : "=r"(r) : "f"(f));
    return r;
}

// m16n8k8 tf32 MMA, C += A*B (row.col)
__device__ __forceinline__ void mma8(float* c, const uint4& a, uint32_t b0, uint32_t b1) {
    asm volatile("mma.sync.aligned.m16n8k8.row.col.f32.tf32.tf32.f32 "
        "{%0,%1,%2,%3}, {%4,%5,%6,%7}, {%8,%9}, {%0,%1,%2,%3};"
        : "+f"(c[0]), "+f"(c[1]), "+f"(c[2]), "+f"(c[3])
        : "r"(a.x), "r"(a.y), "r"(a.z), "r"(a.w), "r"(b0), "r"(b1));
}

// ---------------------------------------------------------------------------
// hstate: h_state[b][j] = state[b] . W1[:512,j] + b1[j]   (exact fp32)
// ---------------------------------------------------------------------------
__global__ __launch_bounds__(256) void hstate_kernel(
    const float* __restrict__ state,
    const float* __restrict__ W1,
    const float* __restrict__ b1)
{
    __shared__ float s[4 * STATE_DIM];
    const int b0 = blockIdx.x * 4;
    const int t = threadIdx.x;
    for (int i = t; i < 4 * STATE_DIM; i += 256)
        s[i] = state[b0 * STATE_DIM + i];
    __syncthreads();

    float a0, a1, a2, a3;
    a0 = a1 = a2 = a3 = b1[t];
#pragma unroll 8
    for (int k = 0; k < STATE_DIM; k++) {
        float w = W1[k * HID + t];
        a0 = fmaf(s[k], w, a0);
        a1 = fmaf(s[512 + k], w, a1);
        a2 = fmaf(s[1024 + k], w, a2);
        a3 = fmaf(s[1536 + k], w, a3);
    }
    g_hstate[(b0 + 0) * HID + t] = a0;
    g_hstate[(b0 + 1) * HID + t] = a1;
    g_hstate[(b0 + 2) * HID + t] = a2;
    g_hstate[(b0 + 3) * HID + t] = a3;
}

// ---------------------------------------------------------------------------
// W1a -> frag order: [ng(4)][ks(8)][np(4)][lane(32)] float4
// float4 = (nt0.b0, nt0.b1, nt1.b0, nt1.b1)
//   b0 = W1a[ks*8 + lane%4     ][colbase + lane/4]
//   b1 = W1a[ks*8 + lane%4 + 4 ][colbase + lane/4]
//   colbase = ng*64 + np*16 (+8 for nt1)
// ---------------------------------------------------------------------------
__global__ __launch_bounds__(256) void prep_w1a(const float* __restrict__ W1) {
    int idx = blockIdx.x * 256 + threadIdx.x;              // 0..16383
    int ri = idx & 3, lane = (idx >> 2) & 31;
    int np = (idx >> 7) & 3, ks = (idx >> 9) & 7, ng = (idx >> 12) & 3;
    int col  = ng * 64 + np * 16 + ((ri & 2) ? 8 : 0) + (lane >> 2);
    int krow = ks * 8 + (lane & 3) + ((ri & 1) ? 4 : 0);
    ((uint32_t*)g_w1af)[idx] = f2tf(W1[(STATE_DIM + krow) * HID + col]);
}

// ---------------------------------------------------------------------------
// Main fused MLP. SMEM (floats):
//   sW2f 32768 | sH1f 16384 | sAf 4096 | sHS 1024 | sB2 128 | sW3 128 | sOut 80
// ---------------------------------------------------------------------------
#define OFF_W2F 0
#define OFF_H1F 32768
#define OFF_AF  49152
#define OFF_HS  53248
#define OFF_B2  54272
#define OFF_W3  54400
#define OFF_OUT 54528
#define SMEM_FLOATS 54608
#define SMEM_BYTES (SMEM_FLOATS * 4)

__global__ void __launch_bounds__(256, 1) actor_main(
    const float* __restrict__ af, const float* __restrict__ W2,
    const float* __restrict__ b2, const float* __restrict__ W3,
    const float* __restrict__ b3, float* __restrict__ out)
{
    extern __shared__ float sm[];
    float* sW2f = sm + OFF_W2F;
    float* sH1f = sm + OFF_H1F;
    float* sAf  = sm + OFF_AF;
    float* sHS  = sm + OFF_HS;     // [2][512]
    float* sB2  = sm + OFF_B2;
    float* sW3  = sm + OFF_W3;
    float* sOut = sm + OFF_OUT;

    const int t = threadIdx.x;
    const int lane = t & 31;
    const int w = t >> 5;
    const int mg = w & 1;          // rows mg*32 .. +31
    const int ng = w >> 1;         // L1: cols ng*64..; L2: cols ng*32..

    // ---- build W2 frags in SMEM: [ng(4)][ks2(32)][np(2)][lane(32)] float4 ----
    for (int i = t; i < 32768; i += 256) {
        int ri = i & 3, ln = (i >> 2) & 31;
        int np = (i >> 7) & 1, ks = (i >> 8) & 31, g = (i >> 13) & 3;
        int col  = g * 32 + np * 16 + ((ri & 2) ? 8 : 0) + (ln >> 2);
        int krow = ks * 8 + (ln & 3) + ((ri & 1) ? 4 : 0);
        ((uint32_t*)sW2f)[i] = f2tf(W2[krow * HID2 + col]);
    }
    if (t < 128) { sB2[t] = b2[t]; sW3[t] = W3[t]; }
    if (t < 64) sOut[t] = 0.f;

    // ---- stage helpers ----
    // A-fragment convention (m16n8k8): reg bit0 = row+8, reg bit1 = k+4
    auto scatter_af = [&](const float4* pf) {
#pragma unroll
        for (int j = 0; j < 4; j++) {
            int fi = (j * 256 + t) * 4;
            const float4 v = pf[j];
#pragma unroll
            for (int e = 0; e < 4; e++) {
                int row = (fi + e) >> 6, feat = (fi + e) & 63;
                int ks = feat >> 3, c = feat & 7;
                int ln = ((row & 7) << 2) | (c & 3);
                int rg = ((row >> 3) & 1) + 2 * (c >> 2);
                float val = (e == 0) ? v.x : (e == 1) ? v.y : (e == 2) ? v.z : v.w;
                ((uint32_t*)sAf)[((((row >> 4) * 8 + ks) * 32 + ln) << 2) + rg] = f2tf(val);
            }
        }
    };
    auto stage_hs = [&](int tl, int buf) {
        int r0 = tl * TILE_M;
        int blo = r0 / KACT;
        int bhi = (r0 + TILE_M - 1) / KACT;
        sHS[buf * 512 + t]       = g_hstate[blo * HID + t];
        sHS[buf * 512 + 256 + t] = g_hstate[bhi * HID + t];
    };

    // ---- prologue: stage first tile ----
    int tile = blockIdx.x;
    {
        float4 pf[4];
        const float4* src = (const float4*)af + (size_t)tile * (TILE_M * AFEAT / 4);
#pragma unroll
        for (int j = 0; j < 4; j++) pf[j] = src[j * 256 + t];
        scatter_af(pf);
        stage_hs(tile, 0);
    }
    __syncthreads();

    const float bias3 = __ldg(b3);
    const uint4* w1v = (const uint4*)g_w1af;
    const uint4* w2v = (const uint4*)sW2f;
    const uint4* afv = (const uint4*)sAf;
    const uint4* h1v = (const uint4*)sH1f;

    int it = 0;
    for (; tile < NTILES; tile += gridDim.x, it++) {
        const int row0 = tile * TILE_M;
        const int ntile = tile + gridDim.x;
        const int cur = it & 1, nxt = cur ^ 1;
        const int split = (row0 / KACT + 1) * KACT - row0;   // rows >= split -> next batch

        // ---- prefetch next tile's af ----
        float4 pf[4];
        if (ntile < NTILES) {
            const float4* src = (const float4*)af + (size_t)ntile * (TILE_M * AFEAT / 4);
#pragma unroll
            for (int j = 0; j < 4; j++) pf[j] = src[j * 256 + t];
        }

        // ---- L1: C = af @ W1a, init C = h_state (exact fp32) ----
        // C-fragment convention (m16n8): reg bit0 = col+1 (parity), reg bit1 = row+8
        float acc[2][8][4];
        const float* hsc = sHS + cur * 512;
#pragma unroll
        for (int ms = 0; ms < 2; ms++)
#pragma unroll
        for (int nt = 0; nt < 8; nt++)
#pragma unroll
        for (int rg = 0; rg < 4; rg++) {
            int r = mg * 32 + ms * 16 + (rg >> 1) * 8 + (lane >> 2);
            int c = ng * 64 + nt * 8 + 2 * (lane & 3) + (rg & 1);
            acc[ms][nt][rg] = hsc[(r >= split ? 256 : 0) + c];
        }
#pragma unroll
        for (int ks = 0; ks < 8; ks++) {
            uint4 a0 = afv[((mg * 2 + 0) * 8 + ks) * 32 + lane];
            uint4 a1 = afv[((mg * 2 + 1) * 8 + ks) * 32 + lane];
#pragma unroll
            for (int np = 0; np < 4; np++) {
                uint4 b = w1v[((ng * 8 + ks) * 4 + np) * 32 + lane];
                mma8(acc[0][np * 2],     a0, b.x, b.y);
                mma8(acc[0][np * 2 + 1], a0, b.z, b.w);
                mma8(acc[1][np * 2],     a1, b.x, b.y);
                mma8(acc[1][np * 2 + 1], a1, b.z, b.w);
            }
        }
        // ---- ep1: relu -> tf32 -> sH1f in L2-A-frag order ----
#pragma unroll
        for (int ms = 0; ms < 2; ms++)
#pragma unroll
        for (int nt = 0; nt < 8; nt++)
#pragma unroll
        for (int rg = 0; rg < 4; rg++) {
            int ks2 = ng * 8 + nt;                       // k (=h1 col) / 8
            int cc  = 2 * (lane & 3) + (rg & 1);         // k within 8-slice
            int ln  = ((lane >> 2) << 2) | (cc & 3);     // (row&7)<<2 | (k&3)
            int rg2 = (rg >> 1) + 2 * (cc >> 2);         // A-conv: bit0=row+8, bit1=k+4
            float v = fmaxf(acc[ms][nt][rg], 0.f);
            ((uint32_t*)sH1f)[((((mg * 2 + ms) * 32 + ks2) * 32 + ln) << 2) + rg2] = f2tf(v);
        }
        __syncthreads();   // S1: h1 ready, afrag free

        // ---- stage next tile while L2 runs ----
        if (ntile < NTILES) {
            scatter_af(pf);
            stage_hs(ntile, nxt);
        }

        // ---- L2: C2 = h1 @ W2 ----
        float acc2[2][4][4];
#pragma unroll
        for (int ms = 0; ms < 2; ms++)
#pragma unroll
        for (int nt = 0; nt < 4; nt++)
#pragma unroll
        for (int rg = 0; rg < 4; rg++) acc2[ms][nt][rg] = 0.f;
#pragma unroll 8
        for (int ks = 0; ks < 32; ks++) {
            uint4 a0 = h1v[((mg * 2 + 0) * 32 + ks) * 32 + lane];
            uint4 a1 = h1v[((mg * 2 + 1) * 32 + ks) * 32 + lane];
#pragma unroll
            for (int np = 0; np < 2; np++) {
                uint4 b = w2v[((ng * 32 + ks) * 2 + np) * 32 + lane];
                mma8(acc2[0][np * 2],     a0, b.x, b.y);
                mma8(acc2[0][np * 2 + 1], a0, b.z, b.w);
                mma8(acc2[1][np * 2],     a1, b.x, b.y);
                mma8(acc2[1][np * 2 + 1], a1, b.z, b.w);
            }
        }

        // ---- L3: out = relu(C2 + b2) . W3 + b3 ----
        float part[2][2] = {{0.f, 0.f}, {0.f, 0.f}};
#pragma unroll
        for (int ms = 0; ms < 2; ms++)
#pragma unroll
        for (int nt = 0; nt < 4; nt++)
#pragma unroll
        for (int rg = 0; rg < 4; rg++) {
            int c = ng * 32 + nt * 8 + 2 * (lane & 3) + (rg & 1);
            float v = fmaxf(acc2[ms][nt][rg] + sB2[c], 0.f);
            part[ms][rg >> 1] += v * sW3[c];             // rg>>1 = row-offset bit
        }
#pragma unroll
        for (int ms = 0; ms < 2; ms++)
#pragma unroll
        for (int rb = 0; rb < 2; rb++) {
            float v = part[ms][rb];
            v += __shfl_xor_sync(0xffffffffu, v, 1);
            v += __shfl_xor_sync(0xffffffffu, v, 2);
            if ((lane & 3) == 0)
                atomicAdd(&sOut[mg * 32 + ms * 16 + rb * 8 + (lane >> 2)], v);
        }
        __syncthreads();   // S2: outstage complete, h1 reads done
        if (t < 64) {
            out[row0 + t] = sOut[t] + bias3;
            sOut[t] = 0.f;
        }
        __syncthreads();   // S3: outstage rezeroed, buffers free
    }
}

// ---------------------------------------------------------------------------
extern "C" void kernel_launch(void* const* d_in, const int* in_sizes, int n_in,
                              void* d_out, int out_size)
{
    const float* state = (const float*)d_in[0];
    const float* afeats = (const float*)d_in[1];
    const float* W1    = (const float*)d_in[2];
    const float* b1    = (const float*)d_in[3];
    const float* W2    = (const float*)d_in[4];
    const float* b2    = (const float*)d_in[5];
    const float* W3    = (const float*)d_in[6];
    const float* b3    = (const float*)d_in[7];
    float* out = (float*)d_out;
    (void)in_sizes; (void)n_in; (void)out_size;

    static int sm_count = 0;
    if (sm_count == 0) {
        cudaDeviceGetAttribute(&sm_count, cudaDevAttrMultiProcessorCount, 0);
        if (sm_count <= 0) sm_count = 148;
        cudaFuncSetAttribute(actor_main,
                             cudaFuncAttributeMaxDynamicSharedMemorySize, SMEM_BYTES);
    }

    prep_w1a<<<64, 256>>>(W1);
    hstate_kernel<<<64, 256>>>(state, W1, b1);
    actor_main<<<sm_count, 256, SMEM_BYTES>>>(afeats, W2, b2, W3, b3, out);
}